// round 11
// baseline (speedup 1.0000x reference)
#include <cuda_runtime.h>
#include <cstdint>

#define GRID_G 128
#define RMIN_F (-1.5f)
#define STEP_F (3.0f / 128.0f)
#define VOXEL_TOTAL (8 * GRID_G * GRID_G * GRID_G * 3)   // 50331648

#define MAX_N   (1 << 20)
#define NB      32                          // 8 t * 4 x-high buckets
#define BSTRIDE 36864                       // slots per bucket (MAX_N/NB + 4096)
#define BPB     (BSTRIDE / 256)             // 144 blocks per bucket
#define BUCKET_ELEMS (32 * GRID_G * GRID_G * 3)  // 1572864 floats per bucket slab
#define BUCKET_F4    (BUCKET_ELEMS / 4)          // 393216 float4 per bucket slab

// __device__ scratch (static allocation; no cudaMalloc)
__device__ int    g_cnt[NB];
__device__ int    g_done[NB];
__device__ float4 g_p4[(size_t)NB * BSTRIDE];   // (pos.xyz, sigma)
__device__ float4 g_t4[(size_t)NB * BSTRIDE];   // (tgt.xyz, bitcast(orig idx))

// ---------------------------------------------------------------------------
// Kernel 0: zero bucket counters + done flags
// ---------------------------------------------------------------------------
__global__ void zero_cnt_kernel() {
    if (threadIdx.x < NB) {
        g_cnt[threadIdx.x]  = 0;
        g_done[threadIdx.x] = 0;
    }
}

// ---------------------------------------------------------------------------
// Kernel 1: bucket-scatter points by (t, x-high)
// ---------------------------------------------------------------------------
__global__ void __launch_bounds__(256)
scatter_kernel(const int* __restrict__ t_arr,
               const float* __restrict__ pos,
               const float* __restrict__ sigma_arr,
               const float* __restrict__ tgt,
               int N) {
    __shared__ int s_cnt[NB];
    __shared__ int s_base[NB];
    int i = blockIdx.x * blockDim.x + threadIdx.x;
    if (threadIdx.x < NB) s_cnt[threadIdx.x] = 0;
    __syncthreads();

    int b = 0, l = 0;
    float4 p4, t4;
    bool valid = (i < N);
    if (valid) {
        float px = pos[3 * i + 0];
        float py = pos[3 * i + 1];
        float pz = pos[3 * i + 2];
        p4 = make_float4(px, py, pz, sigma_arr[i]);
        t4 = make_float4(tgt[3 * i + 0], tgt[3 * i + 1], tgt[3 * i + 2],
                         __int_as_float(i));
        int ix = (int)floorf((px - RMIN_F) / STEP_F);
        int x0 = min(max(ix, 0), GRID_G - 1);
        b = t_arr[i] * 4 + (x0 >> 5);
        l = atomicAdd(&s_cnt[b], 1);
    }
    __syncthreads();
    if (threadIdx.x < NB) {
        int c = s_cnt[threadIdx.x];
        s_base[threadIdx.x] = c ? atomicAdd(&g_cnt[threadIdx.x], c) : 0;
    }
    __syncthreads();
    if (valid) {
        int s = b * BSTRIDE + s_base[b] + l;
        g_p4[s] = p4;
        g_t4[s] = t4;
    }
}

// reduction helpers (no memory clobber: nothing in-kernel reads out_voxel
// values we depend on; copy/RED commutation is argued at the call sites) ----
__device__ __forceinline__ void red_add_f32(float* p, float a) {
    asm volatile("red.global.add.f32 [%0], %1;" :: "l"(p), "f"(a));
}
__device__ __forceinline__ void red_add_v4f32(float* p, float a, float b,
                                              float c, float d) {
    asm volatile("red.global.add.v4.f32 [%0], {%1, %2, %3, %4};"
                 :: "l"(p), "f"(a), "f"(b), "f"(c), "f"(d));
}

// ---------------------------------------------------------------------------
// Shared per-point body (R9): 4 windows in 2 halves.
//   gather:  2x LDG.128 + predicated scalar LDG (off==3)
//   scatter: 2x red.v4  + predicated scalar red (off==3)
// ---------------------------------------------------------------------------
__device__ __forceinline__ void process_point(
    const float* __restrict__ voxel, float* __restrict__ out_voxel,
    float* __restrict__ out_value,
    float px, float py, float pz, float sigma,
    float t0, float t1, float t2, int ti, int orig, float lr)
{
    float sx = px - RMIN_F;
    float sy = py - RMIN_F;
    float sz = pz - RMIN_F;

    int ix = (int)floorf(sx / STEP_F);
    int iy = (int)floorf(sy / STEP_F);
    int iz = (int)floorf(sz / STEP_F);

    float u = fmodf(sx, STEP_F) / STEP_F;
    float v = fmodf(sy, STEP_F) / STEP_F;
    float w = fmodf(sz, STEP_F) / STEP_F;

    int x0 = min(max(ix,     0), GRID_G - 1);
    int x1 = min(max(ix + 1, 0), GRID_G - 1);
    int y0 = min(max(iy,     0), GRID_G - 1);
    int y1 = min(max(iy + 1, 0), GRID_G - 1);
    int z0 = min(max(iz,     0), GRID_G - 1);

    int zb = min(z0, GRID_G - 2);
    int o0 = z0 - zb;                 // 0 normally, 1 at z-top boundary

    float cu0 = 1.0f - u, cv0 = 1.0f - v, cw0 = 1.0f - w;

    float ck0s[4], ck1s[4];
    ck0s[0] = cu0 * cv0 * cw0;  ck1s[0] = cu0 * cv0 * w;   // (x0,y0)
    ck0s[1] = u   * cv0 * cw0;  ck1s[1] = u   * cv0 * w;   // (x1,y0)
    ck0s[2] = cu0 * v   * cw0;  ck1s[2] = cu0 * v   * w;   // (x0,y1)
    ck0s[3] = u   * v   * cw0;  ck1s[3] = u   * v   * w;   // (x1,y1)

    int base_t = ti * (GRID_G * GRID_G * GRID_G);
    int bx0 = base_t + x0 * (GRID_G * GRID_G);
    int bx1 = base_t + x1 * (GRID_G * GRID_G);
    int bs[4];
    bs[0] = bx0 + y0 * GRID_G;
    bs[1] = bx1 + y0 * GRID_G;
    bs[2] = bx0 + y1 * GRID_G;
    bs[3] = bx1 + y1 * GRID_G;

    float sw = 1.0f - __expf(-sigma);
    float scale = lr * sw;

    float val0 = 0.0f, val1 = 0.0f, val2 = 0.0f;

#pragma unroll
    for (int half = 0; half < 2; half++) {
        float4 W[2][2];
        float  w8_[2];
        int    base_[2], off_[2];
        bool   fast_[2];
#pragma unroll
        for (int s = 0; s < 2; s++) {
            int p = 2 * half + s;
            int e    = (bs[p] + zb) * 3;
            int base = e & ~3;
            int off  = e & 3;
            base_[s] = base;
            off_[s]  = off;
            bool f = (base + 12 <= VOXEL_TOTAL);
            fast_[s] = f;
            if (f) {
                const float4* wp = (const float4*)(voxel + base);
                W[s][0] = __ldg(wp + 0);
                W[s][1] = __ldg(wp + 1);
                w8_[s] = (off == 3) ? __ldg(voxel + base + 8) : 0.0f;
            }
        }

#pragma unroll
        for (int s = 0; s < 2; s++) {
            int p = 2 * half + s;
            int base = base_[s];
            int off  = off_[s];
            int e    = base + off;
            bool b0 = (off & 1) != 0;
            bool b1 = (off & 2) != 0;

            float v0x, v0y, v0z, v1x, v1y, v1z;
            if (fast_[s]) {
                float wv[9];
                wv[0] = W[s][0].x; wv[1] = W[s][0].y; wv[2] = W[s][0].z; wv[3] = W[s][0].w;
                wv[4] = W[s][1].x; wv[5] = W[s][1].y; wv[6] = W[s][1].z; wv[7] = W[s][1].w;
                wv[8] = w8_[s];
                float vj[6];
#pragma unroll
                for (int j = 0; j < 6; j++) {
                    float a  = b0 ? wv[j + 1] : wv[j];
                    float bb = b0 ? wv[j + 3] : wv[j + 2];
                    vj[j] = b1 ? bb : a;
                }
                v1x = vj[3]; v1y = vj[4]; v1z = vj[5];
                v0x = o0 ? vj[3] : vj[0];
                v0y = o0 ? vj[4] : vj[1];
                v0z = o0 ? vj[5] : vj[2];
            } else {
                int e0 = e + 3 * o0;
                v0x = __ldg(voxel + e0 + 0);
                v0y = __ldg(voxel + e0 + 1);
                v0z = __ldg(voxel + e0 + 2);
                v1x = __ldg(voxel + e + 3);
                v1y = __ldg(voxel + e + 4);
                v1z = __ldg(voxel + e + 5);
            }

            float ck0 = ck0s[p], ck1 = ck1s[p];
            val0 += ck0 * v0x + ck1 * v1x;
            val1 += ck0 * v0y + ck1 * v1y;
            val2 += ck0 * v0z + ck1 * v1z;

            float lam0 = __fdividef(1.0f, 1.0f + __expf(-scale * ck0));
            float lam1 = __fdividef(1.0f, 1.0f + __expf(-scale * ck1));

            float d00 = lam0 * (t0 - v0x), d01 = lam0 * (t1 - v0y), d02 = lam0 * (t2 - v0z);
            float d10 = lam1 * (t0 - v1x), d11 = lam1 * (t1 - v1y), d12 = lam1 * (t2 - v1z);

            float E0 = o0 ? 0.0f : d00;
            float E1 = o0 ? 0.0f : d01;
            float E2 = o0 ? 0.0f : d02;
            float E3 = o0 ? (d00 + d10) : d10;
            float E4 = o0 ? (d01 + d11) : d11;
            float E5 = o0 ? (d02 + d12) : d12;

            if (fast_[s]) {
                float E[6] = {E0, E1, E2, E3, E4, E5};
                float D[8];
#pragma unroll
                for (int j = 0; j < 8; j++) {
                    float c0 = (j <= 5)            ? E[j > 5 ? 5 : j]                 : 0.0f;
                    float c1 = (j >= 1 && j <= 6)  ? E[(j - 1) > 5 ? 5 : (j - 1)]     : 0.0f;
                    float c2 = (j >= 2 && j <= 7)  ? E[(j - 2) > 5 ? 5 : (j - 2)]     : 0.0f;
                    float c3 = (j >= 3)            ? E[(j - 3) > 5 ? 5 : (j - 3)]     : 0.0f;
                    float a  = b0 ? c1 : c0;
                    float bb = b0 ? c3 : c2;
                    D[j] = b1 ? bb : a;
                }
                float* op = out_voxel + base;
                red_add_v4f32(op + 0, D[0], D[1], D[2], D[3]);
                red_add_v4f32(op + 4, D[4], D[5], D[6], D[7]);
                if (off == 3) red_add_f32(op + 8, E5);
            } else {
                float* op = out_voxel + e;
                red_add_f32(op + 0, E0);
                red_add_f32(op + 1, E1);
                red_add_f32(op + 2, E2);
                red_add_f32(op + 3, E3);
                red_add_f32(op + 4, E4);
                red_add_f32(op + 5, E5);
            }
        }
    }

    out_value[3 * orig + 0] = val0;
    out_value[3 * orig + 1] = val1;
    out_value[3 * orig + 2] = val2;
}

// ---------------------------------------------------------------------------
// Kernel 2 (fused): per-bucket copy + spin-sync + point processing.
// Block (b, r): copies 1/BPB of bucket b's contiguous voxel slab, signals
// done[b], waits for done[b] (and done[b+1] when x-slab < 3), then processes
// its 256 point slots.
// ---------------------------------------------------------------------------
__global__ void __launch_bounds__(256, 5)
fused_main_kernel(const float* __restrict__ lr_p,
                  const float* __restrict__ voxel,
                  float* __restrict__ out_value,
                  float* __restrict__ out_voxel) {
    int b = blockIdx.x / BPB;
    int r = blockIdx.x - b * BPB;

    // ---- copy phase: bucket b's slab, float4-coalesced ----
    {
        const float4* src = (const float4*)voxel + (size_t)b * BUCKET_F4;
        float4* dst = (float4*)out_voxel + (size_t)b * BUCKET_F4;
        for (int j = r * 256 + threadIdx.x; j < BUCKET_F4; j += BPB * 256)
            dst[j] = __ldg(src + j);
    }
    __threadfence();
    __syncthreads();
    if (threadIdx.x == 0) atomicAdd(&g_done[b], 1);

    // ---- wait until this bucket's (and next x-slab's) copy is complete ----
    if (threadIdx.x == 0) {
        volatile int* vd = g_done;
        while (vd[b] < BPB) __nanosleep(64);
        if ((b & 3) != 3) {
            while (vd[b + 1] < BPB) __nanosleep(64);
        }
    }
    __syncthreads();
    __threadfence();

    // ---- point phase ----
    int j = r * 256 + threadIdx.x;
    if (j >= g_cnt[b]) return;
    int g = b * BSTRIDE + j;

    const float lr = __ldg(lr_p);
    float4 p4 = g_p4[g];
    float4 t4 = g_t4[g];
    int ti   = b >> 2;
    int orig = __float_as_int(t4.w);

    process_point(voxel, out_voxel, out_value,
                  p4.x, p4.y, p4.z, p4.w,
                  t4.x, t4.y, t4.z, ti, orig, lr);
}

// ---------------------------------------------------------------------------
// Fallback kernels (N > MAX_N or unexpected voxel size)
// ---------------------------------------------------------------------------
__global__ void voxel_copy_kernel(const float4* __restrict__ src,
                                  float4* __restrict__ dst, int n4) {
    int i = blockIdx.x * blockDim.x + threadIdx.x;
    if (i < n4) dst[i] = src[i];
}

__global__ void __launch_bounds__(256, 5)
point_kernel_direct(const int* __restrict__ t_arr,
                    const float* __restrict__ pos,
                    const float* __restrict__ lr_p,
                    const float* __restrict__ sigma_arr,
                    const float* __restrict__ tgt,
                    const float* __restrict__ voxel,
                    float* __restrict__ out_value,
                    float* __restrict__ out_voxel,
                    int N) {
    int i = blockIdx.x * blockDim.x + threadIdx.x;
    if (i >= N) return;
    const float lr = __ldg(lr_p);
    process_point(voxel, out_voxel, out_value,
                  pos[3 * i], pos[3 * i + 1], pos[3 * i + 2], sigma_arr[i],
                  tgt[3 * i], tgt[3 * i + 1], tgt[3 * i + 2],
                  t_arr[i], i, lr);
}

// ---------------------------------------------------------------------------
// Launch
// Inputs (metadata order): t, pos, lr, sigma, target_norm, voxel_array
// Output: value (N*3 f32) followed by new_voxel (T*G*G*G*3 f32)
// ---------------------------------------------------------------------------
extern "C" void kernel_launch(void* const* d_in, const int* in_sizes, int n_in,
                              void* d_out, int out_size) {
    const int*   t_arr  = (const int*)d_in[0];
    const float* pos    = (const float*)d_in[1];
    const float* lr     = (const float*)d_in[2];
    const float* sigma  = (const float*)d_in[3];
    const float* tgt    = (const float*)d_in[4];
    const float* voxel  = (const float*)d_in[5];

    const int N = in_sizes[0];
    const int voxel_elems = in_sizes[5];

    float* out_value = (float*)d_out;
    float* out_voxel = out_value + (size_t)3 * N;

    const int threads = 256;

    if (N <= MAX_N && voxel_elems == VOXEL_TOTAL) {
        zero_cnt_kernel<<<1, 32>>>();
        {
            int blocks = (N + threads - 1) / threads;
            scatter_kernel<<<blocks, threads>>>(t_arr, pos, sigma, tgt, N);
        }
        fused_main_kernel<<<NB * BPB, threads>>>(lr, voxel,
                                                 out_value, out_voxel);
    } else {
        int n4 = voxel_elems / 4;
        int copy_blocks = (n4 + threads - 1) / threads;
        voxel_copy_kernel<<<copy_blocks, threads>>>((const float4*)voxel,
                                                    (float4*)out_voxel, n4);
        int blocks = (N + threads - 1) / threads;
        point_kernel_direct<<<blocks, threads>>>(t_arr, pos, lr, sigma, tgt,
                                                 voxel, out_value, out_voxel, N);
    }
}

// round 13
// speedup vs baseline: 1.2271x; 1.2271x over previous
#include <cuda_runtime.h>
#include <cstdint>

#define GRID_G 128
#define RMIN_F (-1.5f)
#define STEP_F (3.0f / 128.0f)
#define VOXEL_TOTAL (8 * GRID_G * GRID_G * GRID_G * 3)   // 50331648

#define MAX_N   (1 << 20)
#define NB      32                      // 8 t * 4 x-high buckets
#define BSTRIDE (MAX_N / NB + 4096)     // 36864 slots per bucket

// __device__ scratch (static allocation; no cudaMalloc)
__device__ int    g_cnt[NB];
__device__ float4 g_p4[(size_t)NB * BSTRIDE];   // (pos.xyz, sigma)
__device__ float4 g_t4[(size_t)NB * BSTRIDE];   // (tgt.xyz, unused)
__device__ float4 g_val[(size_t)NB * BSTRIDE];  // per-slot value output
__device__ int    g_slot[MAX_N];                // point i -> slot

// ---------------------------------------------------------------------------
// Kernel 0: zero bucket counters
// ---------------------------------------------------------------------------
__global__ void zero_cnt_kernel() {
    if (threadIdx.x < NB) g_cnt[threadIdx.x] = 0;
}

// ---------------------------------------------------------------------------
// Kernel 1 (fused): blocks [0, SB) bucket-scatter the points; blocks [SB, ...)
// copy voxel_array -> out_voxel (float4).
// ---------------------------------------------------------------------------
__global__ void __launch_bounds__(256)
copy_and_scatter_kernel(const int* __restrict__ t_arr,
                        const float* __restrict__ pos,
                        const float* __restrict__ sigma_arr,
                        const float* __restrict__ tgt,
                        const float4* __restrict__ vsrc,
                        float4* __restrict__ vdst,
                        int N, int SB, int n4) {
    __shared__ int s_cnt[NB];
    __shared__ int s_base[NB];

    if (blockIdx.x >= SB) {
        // ---- copy path ----
        int i = (blockIdx.x - SB) * blockDim.x + threadIdx.x;
        if (i < n4) vdst[i] = vsrc[i];
        return;
    }

    // ---- scatter path ----
    int i = blockIdx.x * blockDim.x + threadIdx.x;
    if (threadIdx.x < NB) s_cnt[threadIdx.x] = 0;
    __syncthreads();

    int b = 0, l = 0;
    float4 p4, t4;
    bool valid = (i < N);
    if (valid) {
        float px = pos[3 * i + 0];
        float py = pos[3 * i + 1];
        float pz = pos[3 * i + 2];
        p4 = make_float4(px, py, pz, sigma_arr[i]);
        t4 = make_float4(tgt[3 * i + 0], tgt[3 * i + 1], tgt[3 * i + 2], 0.0f);
        int ix = (int)floorf((px - RMIN_F) / STEP_F);
        int x0 = min(max(ix, 0), GRID_G - 1);
        b = t_arr[i] * 4 + (x0 >> 5);
        l = atomicAdd(&s_cnt[b], 1);
    }
    __syncthreads();
    if (threadIdx.x < NB) {
        int c = s_cnt[threadIdx.x];
        s_base[threadIdx.x] = c ? atomicAdd(&g_cnt[threadIdx.x], c) : 0;
    }
    __syncthreads();
    if (valid) {
        int s = b * BSTRIDE + s_base[b] + l;
        g_p4[s] = p4;
        g_t4[s] = t4;
        g_slot[i] = s;
    }
}

// reduction helpers (no memory clobber: nothing in-kernel reads out_voxel) ---
__device__ __forceinline__ void red_add_f32(float* p, float a) {
    asm volatile("red.global.add.f32 [%0], %1;" :: "l"(p), "f"(a));
}
__device__ __forceinline__ void red_add_v4f32(float* p, float a, float b,
                                              float c, float d) {
    asm volatile("red.global.add.v4.f32 [%0], {%1, %2, %3, %4};"
                 :: "l"(p), "f"(a), "f"(b), "f"(c), "f"(d));
}

// ---------------------------------------------------------------------------
// Shared per-point body: 4 windows in 2 halves (register control).
//   gather:  2x LDG.128 + predicated scalar LDG (off==3)
//   scatter: 2x red.v4  + predicated scalar red (off==3)
// Value (3 floats) is written to val_dst (contiguous).
// ---------------------------------------------------------------------------
__device__ __forceinline__ void process_point(
    const float* __restrict__ voxel, float* __restrict__ out_voxel,
    float* __restrict__ val_dst,
    float px, float py, float pz, float sigma,
    float t0, float t1, float t2, int ti, float lr)
{
    float sx = px - RMIN_F;
    float sy = py - RMIN_F;
    float sz = pz - RMIN_F;

    int ix = (int)floorf(sx / STEP_F);
    int iy = (int)floorf(sy / STEP_F);
    int iz = (int)floorf(sz / STEP_F);

    float u = fmodf(sx, STEP_F) / STEP_F;
    float v = fmodf(sy, STEP_F) / STEP_F;
    float w = fmodf(sz, STEP_F) / STEP_F;

    int x0 = min(max(ix,     0), GRID_G - 1);
    int x1 = min(max(ix + 1, 0), GRID_G - 1);
    int y0 = min(max(iy,     0), GRID_G - 1);
    int y1 = min(max(iy + 1, 0), GRID_G - 1);
    int z0 = min(max(iz,     0), GRID_G - 1);

    int zb = min(z0, GRID_G - 2);
    int o0 = z0 - zb;                 // 0 normally, 1 at z-top boundary

    float cu0 = 1.0f - u, cv0 = 1.0f - v, cw0 = 1.0f - w;

    float ck0s[4], ck1s[4];
    ck0s[0] = cu0 * cv0 * cw0;  ck1s[0] = cu0 * cv0 * w;   // (x0,y0)
    ck0s[1] = u   * cv0 * cw0;  ck1s[1] = u   * cv0 * w;   // (x1,y0)
    ck0s[2] = cu0 * v   * cw0;  ck1s[2] = cu0 * v   * w;   // (x0,y1)
    ck0s[3] = u   * v   * cw0;  ck1s[3] = u   * v   * w;   // (x1,y1)

    int base_t = ti * (GRID_G * GRID_G * GRID_G);
    int bx0 = base_t + x0 * (GRID_G * GRID_G);
    int bx1 = base_t + x1 * (GRID_G * GRID_G);
    int bs[4];
    bs[0] = bx0 + y0 * GRID_G;
    bs[1] = bx1 + y0 * GRID_G;
    bs[2] = bx0 + y1 * GRID_G;
    bs[3] = bx1 + y1 * GRID_G;

    float sw = 1.0f - __expf(-sigma);
    float scale = lr * sw;

    float val0 = 0.0f, val1 = 0.0f, val2 = 0.0f;

#pragma unroll
    for (int half = 0; half < 2; half++) {
        float4 W[2][2];
        float  w8_[2];
        int    base_[2], off_[2];
        bool   fast_[2];
#pragma unroll
        for (int s = 0; s < 2; s++) {
            int p = 2 * half + s;
            int e    = (bs[p] + zb) * 3;
            int base = e & ~3;
            int off  = e & 3;
            base_[s] = base;
            off_[s]  = off;
            bool f = (base + 12 <= VOXEL_TOTAL);
            fast_[s] = f;
            if (f) {
                const float4* wp = (const float4*)(voxel + base);
                W[s][0] = __ldg(wp + 0);
                W[s][1] = __ldg(wp + 1);
                w8_[s] = (off == 3) ? __ldg(voxel + base + 8) : 0.0f;
            }
        }

#pragma unroll
        for (int s = 0; s < 2; s++) {
            int p = 2 * half + s;
            int base = base_[s];
            int off  = off_[s];
            int e    = base + off;
            bool b0 = (off & 1) != 0;
            bool b1 = (off & 2) != 0;

            float v0x, v0y, v0z, v1x, v1y, v1z;
            if (fast_[s]) {
                float wv[9];
                wv[0] = W[s][0].x; wv[1] = W[s][0].y; wv[2] = W[s][0].z; wv[3] = W[s][0].w;
                wv[4] = W[s][1].x; wv[5] = W[s][1].y; wv[6] = W[s][1].z; wv[7] = W[s][1].w;
                wv[8] = w8_[s];
                float vj[6];
#pragma unroll
                for (int j = 0; j < 6; j++) {
                    float a  = b0 ? wv[j + 1] : wv[j];
                    float bb = b0 ? wv[j + 3] : wv[j + 2];
                    vj[j] = b1 ? bb : a;
                }
                v1x = vj[3]; v1y = vj[4]; v1z = vj[5];
                v0x = o0 ? vj[3] : vj[0];
                v0y = o0 ? vj[4] : vj[1];
                v0z = o0 ? vj[5] : vj[2];
            } else {
                int e0 = e + 3 * o0;
                v0x = __ldg(voxel + e0 + 0);
                v0y = __ldg(voxel + e0 + 1);
                v0z = __ldg(voxel + e0 + 2);
                v1x = __ldg(voxel + e + 3);
                v1y = __ldg(voxel + e + 4);
                v1z = __ldg(voxel + e + 5);
            }

            float ck0 = ck0s[p], ck1 = ck1s[p];
            val0 += ck0 * v0x + ck1 * v1x;
            val1 += ck0 * v0y + ck1 * v1y;
            val2 += ck0 * v0z + ck1 * v1z;

            float lam0 = __fdividef(1.0f, 1.0f + __expf(-scale * ck0));
            float lam1 = __fdividef(1.0f, 1.0f + __expf(-scale * ck1));

            float d00 = lam0 * (t0 - v0x), d01 = lam0 * (t1 - v0y), d02 = lam0 * (t2 - v0z);
            float d10 = lam1 * (t0 - v1x), d11 = lam1 * (t1 - v1y), d12 = lam1 * (t2 - v1z);

            float E0 = o0 ? 0.0f : d00;
            float E1 = o0 ? 0.0f : d01;
            float E2 = o0 ? 0.0f : d02;
            float E3 = o0 ? (d00 + d10) : d10;
            float E4 = o0 ? (d01 + d11) : d11;
            float E5 = o0 ? (d02 + d12) : d12;

            if (fast_[s]) {
                float E[6] = {E0, E1, E2, E3, E4, E5};
                float D[8];
#pragma unroll
                for (int j = 0; j < 8; j++) {
                    float c0 = (j <= 5)            ? E[j > 5 ? 5 : j]                 : 0.0f;
                    float c1 = (j >= 1 && j <= 6)  ? E[(j - 1) > 5 ? 5 : (j - 1)]     : 0.0f;
                    float c2 = (j >= 2 && j <= 7)  ? E[(j - 2) > 5 ? 5 : (j - 2)]     : 0.0f;
                    float c3 = (j >= 3)            ? E[(j - 3) > 5 ? 5 : (j - 3)]     : 0.0f;
                    float a  = b0 ? c1 : c0;
                    float bb = b0 ? c3 : c2;
                    D[j] = b1 ? bb : a;
                }
                float* op = out_voxel + base;
                red_add_v4f32(op + 0, D[0], D[1], D[2], D[3]);
                red_add_v4f32(op + 4, D[4], D[5], D[6], D[7]);
                if (off == 3) red_add_f32(op + 8, E5);
            } else {
                float* op = out_voxel + e;
                red_add_f32(op + 0, E0);
                red_add_f32(op + 1, E1);
                red_add_f32(op + 2, E2);
                red_add_f32(op + 3, E3);
                red_add_f32(op + 4, E4);
                red_add_f32(op + 5, E5);
            }
        }
    }

    val_dst[0] = val0;
    val_dst[1] = val1;
    val_dst[2] = val2;
}

// ---------------------------------------------------------------------------
// Kernel 2: bucketed main kernel — value written COALESCED to g_val[slot]
// ---------------------------------------------------------------------------
__global__ void __launch_bounds__(256, 5)
point_kernel_bucketed(const float* __restrict__ lr_p,
                      const float* __restrict__ voxel,
                      float* __restrict__ out_voxel) {
    int g = blockIdx.x * blockDim.x + threadIdx.x;
    int b = g / BSTRIDE;
    int j = g - b * BSTRIDE;
    if (b >= NB || j >= g_cnt[b]) return;

    const float lr = __ldg(lr_p);
    float4 p4 = g_p4[g];
    float4 t4 = g_t4[g];
    int ti = b >> 2;

    process_point(voxel, out_voxel, (float*)&g_val[g],
                  p4.x, p4.y, p4.z, p4.w,
                  t4.x, t4.y, t4.z, ti, lr);
}

// ---------------------------------------------------------------------------
// Kernel 3: reorder values back to original point order
// ---------------------------------------------------------------------------
__global__ void __launch_bounds__(256)
reorder_kernel(float* __restrict__ out_value, int N) {
    int i = blockIdx.x * blockDim.x + threadIdx.x;
    if (i >= N) return;
    int s = g_slot[i];
    float4 v = g_val[s];
    out_value[3 * i + 0] = v.x;
    out_value[3 * i + 1] = v.y;
    out_value[3 * i + 2] = v.z;
}

// ---------------------------------------------------------------------------
// Fallback kernels (N > MAX_N): direct path writes value straight out
// ---------------------------------------------------------------------------
__global__ void voxel_copy_kernel(const float4* __restrict__ src,
                                  float4* __restrict__ dst, int n4) {
    int i = blockIdx.x * blockDim.x + threadIdx.x;
    if (i < n4) dst[i] = src[i];
}

__global__ void __launch_bounds__(256, 5)
point_kernel_direct(const int* __restrict__ t_arr,
                    const float* __restrict__ pos,
                    const float* __restrict__ lr_p,
                    const float* __restrict__ sigma_arr,
                    const float* __restrict__ tgt,
                    const float* __restrict__ voxel,
                    float* __restrict__ out_value,
                    float* __restrict__ out_voxel,
                    int N) {
    int i = blockIdx.x * blockDim.x + threadIdx.x;
    if (i >= N) return;
    const float lr = __ldg(lr_p);
    process_point(voxel, out_voxel, out_value + 3 * i,
                  pos[3 * i], pos[3 * i + 1], pos[3 * i + 2], sigma_arr[i],
                  tgt[3 * i], tgt[3 * i + 1], tgt[3 * i + 2],
                  t_arr[i], lr);
}

// ---------------------------------------------------------------------------
// Launch
// Inputs (metadata order): t, pos, lr, sigma, target_norm, voxel_array
// Output: value (N*3 f32) followed by new_voxel (T*G*G*G*3 f32)
// ---------------------------------------------------------------------------
extern "C" void kernel_launch(void* const* d_in, const int* in_sizes, int n_in,
                              void* d_out, int out_size) {
    const int*   t_arr  = (const int*)d_in[0];
    const float* pos    = (const float*)d_in[1];
    const float* lr     = (const float*)d_in[2];
    const float* sigma  = (const float*)d_in[3];
    const float* tgt    = (const float*)d_in[4];
    const float* voxel  = (const float*)d_in[5];

    const int N = in_sizes[0];
    const int voxel_elems = in_sizes[5];

    float* out_value = (float*)d_out;
    float* out_voxel = out_value + (size_t)3 * N;

    const int threads = 256;
    const int n4 = voxel_elems / 4;
    const int copy_blocks = (n4 + threads - 1) / threads;

    if (N <= MAX_N) {
        zero_cnt_kernel<<<1, 32>>>();
        {
            int SB = (N + threads - 1) / threads;
            copy_and_scatter_kernel<<<SB + copy_blocks, threads>>>(
                t_arr, pos, sigma, tgt,
                (const float4*)voxel, (float4*)out_voxel, N, SB, n4);
        }
        {
            long long total = (long long)NB * BSTRIDE;
            int blocks = (int)((total + threads - 1) / threads);
            point_kernel_bucketed<<<blocks, threads>>>(lr, voxel, out_voxel);
        }
        {
            int blocks = (N + threads - 1) / threads;
            reorder_kernel<<<blocks, threads>>>(out_value, N);
        }
    } else {
        voxel_copy_kernel<<<copy_blocks, threads>>>((const float4*)voxel,
                                                    (float4*)out_voxel, n4);
        int blocks = (N + threads - 1) / threads;
        point_kernel_direct<<<blocks, threads>>>(t_arr, pos, lr, sigma, tgt,
                                                 voxel, out_value, out_voxel, N);
    }
}